// round 6
// baseline (speedup 1.0000x reference)
#include <cuda_runtime.h>
#include <math.h>

#define NN 4096
#define DD 256
#define KK 32
#define LL 4
#define TT 100
#define PP 64
#define BB 32
#define CIN 420
#define CINP 432   // padded to multiple of 16
#define NSTATE 5

// ---- weight offsets in the split-weight buffers ----
#define OFF_WIN    0
#define SZ_WIN     (CINP*DD)
#define OFF_WSELF  (OFF_WIN + SZ_WIN)
#define SZ_WSELF   (LL*DD*DD)
#define OFF_WCONV  (OFF_WSELF + SZ_WSELF)
#define SZ_WCONV   (LL*DD*DD)
#define OFF_WCAT   (OFF_WCONV + SZ_WCONV)
#define SZ_WCAT    (LL*2*DD*DD)
#define OFF_WOUT   (OFF_WCAT + SZ_WCAT)
#define SZ_WOUT    (NSTATE*DD*DD)
#define OFF_WNOISE (OFF_WOUT + SZ_WOUT)
#define SZ_WNOISE  (DD*DD)
#define OFF_WRAD   (OFF_WNOISE + SZ_WNOISE)
#define SZ_WRAD    (LL*BB*DD)
#define TOTW       (OFF_WRAD + SZ_WRAD)

// ---------------- scratch (device globals; no allocations) ----------------
__device__ float g_inh[NN * CINP], g_inl[NN * CINP];
__device__ float g_cath[NN * 2 * DD], g_catl[NN * 2 * DD];
__device__ float g_hs[NN * DD];
__device__ float g_msgh[NN * DD], g_msgl[NN * DD];
__device__ float g_sth[NN * NSTATE * DD], g_stl[NN * NSTATE * DD];
__device__ float g_out[NN * DD], g_outh[NN * DD], g_outl[NN * DD];
__device__ int   g_idx[NN * KK];
__device__ float g_ed[NN * KK];
__device__ float g_rbfh[NN * KK * BB], g_rbfl[NN * KK * BB];
__device__ float g_sx[NN], g_sy[NN], g_sz[NN];
__device__ float g_whi[TOTW], g_wlo[TOTW];

// ---------------- helpers ----------------
__device__ __forceinline__ float f2tf(float x) {
    unsigned r;
    asm("cvt.rna.tf32.f32 %0, %1;" : "=r"(r) : "f"(x));
    return __uint_as_float(r);
}
__device__ __forceinline__ void split2f(float f, float& hi, float& lo) {
    hi = f2tf(f);
    lo = f2tf(f - hi);
}
__device__ __forceinline__ void mma_tf32(float& d0, float& d1, float& d2, float& d3,
                                         unsigned a0, unsigned a1, unsigned a2, unsigned a3,
                                         unsigned b0, unsigned b1) {
    asm volatile(
        "mma.sync.aligned.m16n8k8.row.col.f32.tf32.tf32.f32 "
        "{%0,%1,%2,%3}, {%4,%5,%6,%7}, {%8,%9}, {%0,%1,%2,%3};"
        : "+f"(d0), "+f"(d1), "+f"(d2), "+f"(d3)
        : "r"(a0), "r"(a1), "r"(a2), "r"(a3), "r"(b0), "r"(b1));
}

// ---------------- weight split prologue ----------------
__global__ void splitw_kernel(const float* __restrict__ src,
                              float* __restrict__ hi, float* __restrict__ lo,
                              int n, int nsrc) {
    int t = blockIdx.x * 256 + threadIdx.x;
    if (t >= n) return;
    float v = (t < nsrc) ? src[t] : 0.0f;
    float h, l;
    split2f(v, h, l);
    hi[t] = h;
    lo[t] = l;
}

// ---------------- input build (pre-split, padded) ----------------
__global__ void build_in_kernel(const float* __restrict__ feat,
                                const float* __restrict__ pos,
                                const float* __restrict__ mask,
                                const float* __restrict__ tptr,
                                float* __restrict__ outh,
                                float* __restrict__ outl) {
    int i = blockIdx.x;
    float t = *tptr;
    float mk = mask[i];
    for (int c = threadIdx.x; c < CINP; c += blockDim.x) {
        float v;
        if (c < TT) {
            float d = (t - (float)c * (1.0f / 99.0f)) * 99.0f;
            float a = fabsf(d);
            if (a < 1.0f) {
                float cc = cospif(0.5f * d);
                v = cc * cc * mk;
            } else v = 0.0f;
        } else if (c < TT + DD) {
            v = feat[i * DD + (c - TT)];
        } else if (c < CIN) {
            v = pos[i * PP + (c - TT - DD)];
        } else {
            v = 0.0f;   // pad
        }
        float h, l;
        split2f(v, h, l);
        outh[(size_t)i * CINP + c] = h;
        outl[(size_t)i * CINP + c] = l;
    }
}

// ---------------- SoA coord transpose ----------------
__global__ void soa_kernel(const float* __restrict__ coord,
                           float* __restrict__ gx, float* __restrict__ gy,
                           float* __restrict__ gz) {
    int j = blockIdx.x * 256 + threadIdx.x;
    if (j < NN) {
        gx[j] = coord[j * 3 + 0];
        gy[j] = coord[j * 3 + 1];
        gz[j] = coord[j * 3 + 2];
    }
}

// ---------------- kNN: register distances, lazy re-reduce ----------------
__global__ __launch_bounds__(256) void knn_kernel(const float* __restrict__ gx,
                                                  const float* __restrict__ gy,
                                                  const float* __restrict__ gz,
                                                  int* __restrict__ idx_out,
                                                  float* __restrict__ ed_out) {
    __shared__ float wv[8];
    __shared__ int wi[8];
    __shared__ int s_sel;
    int i = blockIdx.x;
    int tid = threadIdx.x;
    int lane = tid & 31;
    int warp = tid >> 5;
    float cx = gx[i], cy = gy[i], cz = gz[i];
    float d2r[16];
    unsigned exm = 0;
    float v = 3.4e38f;
    int bi = 0x7FFFFFFF;
    #pragma unroll
    for (int s = 0; s < 16; s++) {
        int j = tid + s * 256;
        float dx = cx - gx[j];
        float dy = cy - gy[j];
        float dz = cz - gz[j];
        float d2 = dx * dx + dy * dy + dz * dz;
        if (j == i) d2 += 1e9f;
        d2r[s] = d2;
        if (d2 < v) { v = d2; bi = j; }
    }
    // initial per-warp reduce
    {
        float rv = v; int rb = bi;
        #pragma unroll
        for (int o = 16; o > 0; o >>= 1) {
            float ov = __shfl_down_sync(0xFFFFFFFFu, rv, o);
            int ob = __shfl_down_sync(0xFFFFFFFFu, rb, o);
            if (ov < rv || (ov == rv && ob < rb)) { rv = ov; rb = ob; }
        }
        if (lane == 0) { wv[warp] = rv; wi[warp] = rb; }
    }
    __syncthreads();
    for (int kk = 0; kk < KK; kk++) {
        if (warp == 0) {
            float v2 = (lane < 8) ? wv[lane] : 3.4e38f;
            int b2 = (lane < 8) ? wi[lane] : 0x7FFFFFFF;
            #pragma unroll
            for (int o = 4; o > 0; o >>= 1) {
                float ov = __shfl_down_sync(0xFFFFFFFFu, v2, o);
                int ob = __shfl_down_sync(0xFFFFFFFFu, b2, o);
                if (ov < v2 || (ov == v2 && ob < b2)) { v2 = ov; b2 = ob; }
            }
            if (lane == 0) {
                idx_out[i * KK + kk] = b2;
                ed_out[i * KK + kk] = sqrtf(fmaxf(v2, 1e-12f));
                s_sel = b2;
            }
        }
        __syncthreads();
        int b = s_sel;
        int owner = b & 255;
        if (tid == owner) {
            exm |= 1u << ((b - tid) >> 8);
            v = 3.4e38f; bi = 0x7FFFFFFF;
            #pragma unroll
            for (int s = 0; s < 16; s++) {
                float d2 = d2r[s];
                bool live = ((exm >> s) & 1u) == 0u;
                if (live && d2 < v) { v = d2; bi = tid + s * 256; }
            }
        }
        if (kk + 1 < KK && warp == (owner >> 5)) {
            float rv = v; int rb = bi;
            #pragma unroll
            for (int o = 16; o > 0; o >>= 1) {
                float ov = __shfl_down_sync(0xFFFFFFFFu, rv, o);
                int ob = __shfl_down_sync(0xFFFFFFFFu, rb, o);
                if (ov < rv || (ov == rv && ob < rb)) { rv = ov; rb = ob; }
            }
            if (lane == 0) { wv[warp] = rv; wi[warp] = rb; }
        }
        __syncthreads();
    }
}

// ---------------- gaussian RBF (pre-split output) ----------------
__global__ void rbf_kernel(const float* __restrict__ ed,
                           float* __restrict__ rbfh, float* __restrict__ rbfl) {
    int t = blockIdx.x * blockDim.x + threadIdx.x;
    if (t >= NN * KK * BB) return;
    int b = t & (BB - 1);
    int ik = t >> 5;
    float d = ed[ik];
    float c = 32.0f * (float)b * (1.0f / 31.0f);
    float x = d - c;
    float r = expf(-x * x);
    float h, l;
    split2f(r, h, l);
    rbfh[t] = h;
    rbfl[t] = l;
}

// ================= split-tf32 GEMM with optional LN epilogue =================
// Block tile 32 x 256 (full rows), BK=16, 8 warps (warp tile 32x32).
// All operands pre-split (hi/lo) in global memory -> inner loop is LDS + MMA only.
#define GBK 16
#define AST2 20   // A smem stride (16 k + 4 pad)
#define BST 264   // B smem stride (256 n + 8 pad)

template <bool DO_LN>
__global__ __launch_bounds__(256) void gemm_ln_kernel(
    const float* __restrict__ Ahi, const float* __restrict__ Alo, int lda,
    const float* __restrict__ Bhi, const float* __restrict__ Blo, int Kd,
    float* __restrict__ Cf, int ldcf,
    float* __restrict__ Chi, float* __restrict__ Clo, int ldc2,
    float* __restrict__ Shi, float* __restrict__ Slo, int scol,
    const float* __restrict__ mask) {
    __shared__ float sA[2 * 32 * AST2];    // hi | lo
    __shared__ float sB[2 * GBK * BST];    // hi | lo ; reused as 32xBST LN staging
    float* Ash = sA;
    float* Asl = sA + 32 * AST2;
    float* Bsh = sB;
    float* Bsl = sB + GBK * BST;
    int tid = threadIdx.x;
    int bm = blockIdx.x * 32;
    int warp = tid >> 5, lane = tid & 31;
    int gid = lane >> 2, tig = lane & 3;

    // A loader: threads 0..127 load hi, 128..255 load lo; 128 float4 covers 32x16
    int aidx = tid & 127;
    int arow = aidx >> 2;
    int ac4 = (aidx & 3) * 4;
    const float* Asrc = (tid < 128 ? Ahi : Alo) + (size_t)(bm + arow) * lda + ac4;
    float* Adst = (tid < 128 ? Ash : Asl) + arow * AST2 + ac4;

    float4 avr, bvh[4], bvl[4];
    auto load_tile = [&](int k0) {
        avr = *reinterpret_cast<const float4*>(Asrc + k0);
        #pragma unroll
        for (int it = 0; it < 4; it++) {
            int idx = it * 256 + tid;
            int r = idx >> 6;
            int c4 = (idx & 63) * 4;
            bvh[it] = *reinterpret_cast<const float4*>(Bhi + (size_t)(k0 + r) * DD + c4);
            bvl[it] = *reinterpret_cast<const float4*>(Blo + (size_t)(k0 + r) * DD + c4);
        }
    };
    auto store_tile = [&]() {
        *reinterpret_cast<float4*>(Adst) = avr;
        #pragma unroll
        for (int it = 0; it < 4; it++) {
            int idx = it * 256 + tid;
            int r = idx >> 6;
            int c4 = (idx & 63) * 4;
            *reinterpret_cast<float4*>(&Bsh[r * BST + c4]) = bvh[it];
            *reinterpret_cast<float4*>(&Bsl[r * BST + c4]) = bvl[it];
        }
    };

    float cf[2][4][4];
    #pragma unroll
    for (int mt = 0; mt < 2; mt++)
        #pragma unroll
        for (int nt = 0; nt < 4; nt++)
            #pragma unroll
            for (int q = 0; q < 4; q++) cf[mt][nt][q] = 0.0f;

    load_tile(0);
    store_tile();
    __syncthreads();

    for (int k0 = 0;;) {
        int kn = k0 + GBK;
        bool more = kn < Kd;
        if (more) load_tile(kn);
        #pragma unroll
        for (int ks = 0; ks < 2; ks++) {
            int kc = ks * 8 + tig;
            unsigned ah[2][4], al[2][4];
            #pragma unroll
            for (int mt = 0; mt < 2; mt++) {
                int r = gid + mt * 16;
                ah[mt][0] = __float_as_uint(Ash[r * AST2 + kc]);
                ah[mt][1] = __float_as_uint(Ash[(r + 8) * AST2 + kc]);
                ah[mt][2] = __float_as_uint(Ash[r * AST2 + kc + 4]);
                ah[mt][3] = __float_as_uint(Ash[(r + 8) * AST2 + kc + 4]);
                al[mt][0] = __float_as_uint(Asl[r * AST2 + kc]);
                al[mt][1] = __float_as_uint(Asl[(r + 8) * AST2 + kc]);
                al[mt][2] = __float_as_uint(Asl[r * AST2 + kc + 4]);
                al[mt][3] = __float_as_uint(Asl[(r + 8) * AST2 + kc + 4]);
            }
            unsigned bh[4][2], bl[4][2];
            #pragma unroll
            for (int nt = 0; nt < 4; nt++) {
                int cb = warp * 32 + nt * 8 + gid;
                bh[nt][0] = __float_as_uint(Bsh[(ks * 8 + tig) * BST + cb]);
                bh[nt][1] = __float_as_uint(Bsh[(ks * 8 + tig + 4) * BST + cb]);
                bl[nt][0] = __float_as_uint(Bsl[(ks * 8 + tig) * BST + cb]);
                bl[nt][1] = __float_as_uint(Bsl[(ks * 8 + tig + 4) * BST + cb]);
            }
            #pragma unroll
            for (int mt = 0; mt < 2; mt++)
                #pragma unroll
                for (int nt = 0; nt < 4; nt++) {
                    mma_tf32(cf[mt][nt][0], cf[mt][nt][1], cf[mt][nt][2], cf[mt][nt][3],
                             ah[mt][0], ah[mt][1], ah[mt][2], ah[mt][3],
                             bh[nt][0], bh[nt][1]);
                    mma_tf32(cf[mt][nt][0], cf[mt][nt][1], cf[mt][nt][2], cf[mt][nt][3],
                             ah[mt][0], ah[mt][1], ah[mt][2], ah[mt][3],
                             bl[nt][0], bl[nt][1]);
                    mma_tf32(cf[mt][nt][0], cf[mt][nt][1], cf[mt][nt][2], cf[mt][nt][3],
                             al[mt][0], al[mt][1], al[mt][2], al[mt][3],
                             bh[nt][0], bh[nt][1]);
                }
        }
        if (!more) break;
        __syncthreads();
        store_tile();
        __syncthreads();
        k0 = kn;
    }

    if (!DO_LN) {
        #pragma unroll
        for (int mt = 0; mt < 2; mt++)
            #pragma unroll
            for (int nt = 0; nt < 4; nt++) {
                int r0 = bm + gid + mt * 16;
                int c = warp * 32 + nt * 8 + tig * 2;
                #pragma unroll
                for (int q = 0; q < 4; q++) {
                    int r = (q < 2) ? r0 : r0 + 8;
                    int cc = c + (q & 1);
                    float vv = cf[mt][nt][q];
                    if (Cf) Cf[(size_t)r * ldcf + cc] = vv;
                    if (Chi) {
                        float h, l;
                        split2f(vv, h, l);
                        Chi[(size_t)r * ldc2 + cc] = h;
                        Clo[(size_t)r * ldc2 + cc] = l;
                    }
                }
            }
        return;
    }

    // ---- LN epilogue ----
    float* stage = sB;   // 32 x BST staging (exactly 2*GBK*BST)
    __syncthreads();
    #pragma unroll
    for (int mt = 0; mt < 2; mt++)
        #pragma unroll
        for (int nt = 0; nt < 4; nt++) {
            int r = gid + mt * 16;
            int c = warp * 32 + nt * 8 + tig * 2;
            stage[r * BST + c]           = cf[mt][nt][0];
            stage[r * BST + c + 1]       = cf[mt][nt][1];
            stage[(r + 8) * BST + c]     = cf[mt][nt][2];
            stage[(r + 8) * BST + c + 1] = cf[mt][nt][3];
        }
    __syncthreads();

    int row = tid >> 3;
    int sub = tid & 7;
    float s = 0.0f, s2 = 0.0f;
    #pragma unroll
    for (int j = 0; j < 32; j++) {
        float x = stage[row * BST + sub + j * 8];
        s += x;
        s2 += x * x;
    }
    #pragma unroll
    for (int o = 4; o > 0; o >>= 1) {
        s  += __shfl_xor_sync(0xFFFFFFFFu, s, o);
        s2 += __shfl_xor_sync(0xFFFFFFFFu, s2, o);
    }
    float mean = s * (1.0f / DD);
    float var = s2 * (1.0f / DD) - mean * mean;
    float scale = rsqrtf(var + 1e-5f);
    int i = bm + row;
    float mk = mask ? mask[i] : 1.0f;
    #pragma unroll
    for (int j = 0; j < 32; j++) {
        int c = sub + j * 8;
        float y = (stage[row * BST + c] - mean) * scale * mk;
        if (Cf) Cf[(size_t)i * ldcf + c] = y;
        if (Chi) {
            float h, l;
            split2f(y, h, l);
            Chi[(size_t)i * ldc2 + c] = h;
            Clo[(size_t)i * ldc2 + c] = l;
            if (Shi) {
                Shi[(size_t)i * (NSTATE * DD) + scol * DD + c] = h;
                Slo[(size_t)i * (NSTATE * DD) + scol * DD + c] = l;
            }
        }
    }
}

// ================= tensor-core message kernel (pre-split operands) =================
#define MAST 36
#define MSG_SMEM ((2 * 32 * MAST + 2 * 32 * BST) * 4)

__global__ __launch_bounds__(256) void msg_mma_kernel(const float* __restrict__ h,
                                                      const int* __restrict__ idx,
                                                      const float* __restrict__ rbfh,
                                                      const float* __restrict__ rbfl,
                                                      const float* __restrict__ Wh,
                                                      const float* __restrict__ Wl,
                                                      float* __restrict__ outh,
                                                      float* __restrict__ outl) {
    extern __shared__ float dyn[];
    float* Ash = dyn;
    float* Asl = Ash + 32 * MAST;
    float* Bsh = Asl + 32 * MAST;
    float* Bsl = Bsh + 32 * BST;
    __shared__ int js[KK];
    int i = blockIdx.x;
    int tid = threadIdx.x;
    int warp = tid >> 5, lane = tid & 31;
    int gid = lane >> 2, tig = lane & 3;

    {
        int r = tid >> 3;
        int b4 = (tid & 7) * 4;
        *reinterpret_cast<float4*>(&Ash[r * MAST + b4]) =
            *reinterpret_cast<const float4*>(rbfh + (size_t)i * (KK * BB) + r * BB + b4);
        *reinterpret_cast<float4*>(&Asl[r * MAST + b4]) =
            *reinterpret_cast<const float4*>(rbfl + (size_t)i * (KK * BB) + r * BB + b4);
    }
    #pragma unroll
    for (int it = 0; it < 8; it++) {
        int idx2 = it * 256 + tid;
        int r = idx2 >> 6;
        int c4 = (idx2 & 63) * 4;
        *reinterpret_cast<float4*>(&Bsh[r * BST + c4]) =
            *reinterpret_cast<const float4*>(Wh + (size_t)r * DD + c4);
        *reinterpret_cast<float4*>(&Bsl[r * BST + c4]) =
            *reinterpret_cast<const float4*>(Wl + (size_t)r * DD + c4);
    }
    if (tid < KK) js[tid] = idx[i * KK + tid];
    __syncthreads();

    float cf[2][4][4];
    #pragma unroll
    for (int mt = 0; mt < 2; mt++)
        #pragma unroll
        for (int nt = 0; nt < 4; nt++)
            #pragma unroll
            for (int q = 0; q < 4; q++) cf[mt][nt][q] = 0.0f;

    #pragma unroll
    for (int ks = 0; ks < 4; ks++) {
        int kc = ks * 8 + tig;
        unsigned ah[2][4], al[2][4];
        #pragma unroll
        for (int mt = 0; mt < 2; mt++) {
            int r = gid + mt * 16;
            ah[mt][0] = __float_as_uint(Ash[r * MAST + kc]);
            ah[mt][1] = __float_as_uint(Ash[(r + 8) * MAST + kc]);
            ah[mt][2] = __float_as_uint(Ash[r * MAST + kc + 4]);
            ah[mt][3] = __float_as_uint(Ash[(r + 8) * MAST + kc + 4]);
            al[mt][0] = __float_as_uint(Asl[r * MAST + kc]);
            al[mt][1] = __float_as_uint(Asl[(r + 8) * MAST + kc]);
            al[mt][2] = __float_as_uint(Asl[r * MAST + kc + 4]);
            al[mt][3] = __float_as_uint(Asl[(r + 8) * MAST + kc + 4]);
        }
        unsigned bh[4][2], bl[4][2];
        #pragma unroll
        for (int nt = 0; nt < 4; nt++) {
            int cb = warp * 32 + nt * 8 + gid;
            bh[nt][0] = __float_as_uint(Bsh[(ks * 8 + tig) * BST + cb]);
            bh[nt][1] = __float_as_uint(Bsh[(ks * 8 + tig + 4) * BST + cb]);
            bl[nt][0] = __float_as_uint(Bsl[(ks * 8 + tig) * BST + cb]);
            bl[nt][1] = __float_as_uint(Bsl[(ks * 8 + tig + 4) * BST + cb]);
        }
        #pragma unroll
        for (int mt = 0; mt < 2; mt++)
            #pragma unroll
            for (int nt = 0; nt < 4; nt++) {
                mma_tf32(cf[mt][nt][0], cf[mt][nt][1], cf[mt][nt][2], cf[mt][nt][3],
                         ah[mt][0], ah[mt][1], ah[mt][2], ah[mt][3],
                         bh[nt][0], bh[nt][1]);
                mma_tf32(cf[mt][nt][0], cf[mt][nt][1], cf[mt][nt][2], cf[mt][nt][3],
                         ah[mt][0], ah[mt][1], ah[mt][2], ah[mt][3],
                         bl[nt][0], bl[nt][1]);
                mma_tf32(cf[mt][nt][0], cf[mt][nt][1], cf[mt][nt][2], cf[mt][nt][3],
                         al[mt][0], al[mt][1], al[mt][2], al[mt][3],
                         bh[nt][0], bh[nt][1]);
            }
    }
    __syncthreads();

    // gather H rows into Bsh region
    #pragma unroll
    for (int it = 0; it < 8; it++) {
        int idx2 = it * 256 + tid;
        int r = idx2 >> 6;
        int c4 = (idx2 & 63) * 4;
        int j = js[r];
        *reinterpret_cast<float4*>(&Bsh[r * BST + c4]) =
            *reinterpret_cast<const float4*>(h + (size_t)j * DD + c4);
    }
    __syncthreads();

    float sacc[4][2];
    #pragma unroll
    for (int nt = 0; nt < 4; nt++) { sacc[nt][0] = 0.0f; sacc[nt][1] = 0.0f; }
    #pragma unroll
    for (int mt = 0; mt < 2; mt++) {
        int r = gid + mt * 16;
        #pragma unroll
        for (int nt = 0; nt < 4; nt++) {
            int c = warp * 32 + nt * 8 + tig * 2;
            sacc[nt][0] += cf[mt][nt][0] * Bsh[r * BST + c];
            sacc[nt][1] += cf[mt][nt][1] * Bsh[r * BST + c + 1];
            sacc[nt][0] += cf[mt][nt][2] * Bsh[(r + 8) * BST + c];
            sacc[nt][1] += cf[mt][nt][3] * Bsh[(r + 8) * BST + c + 1];
        }
    }
    #pragma unroll
    for (int o = 4; o <= 16; o <<= 1) {
        #pragma unroll
        for (int nt = 0; nt < 4; nt++) {
            sacc[nt][0] += __shfl_xor_sync(0xFFFFFFFFu, sacc[nt][0], o);
            sacc[nt][1] += __shfl_xor_sync(0xFFFFFFFFu, sacc[nt][1], o);
        }
    }
    if (gid == 0) {
        #pragma unroll
        for (int nt = 0; nt < 4; nt++) {
            int c = warp * 32 + nt * 8 + tig * 2;
            float v0 = sacc[nt][0] * (1.0f / KK);
            float v1 = sacc[nt][1] * (1.0f / KK);
            float h0, l0, h1, l1;
            split2f(v0, h0, l0);
            split2f(v1, h1, l1);
            outh[(size_t)i * DD + c]     = h0;
            outl[(size_t)i * DD + c]     = l0;
            outh[(size_t)i * DD + c + 1] = h1;
            outl[(size_t)i * DD + c + 1] = l1;
        }
    }
}

// ---------------- coord head ----------------
__global__ void coord_out_kernel(const float* __restrict__ out,
                                 const float* __restrict__ Wc,
                                 float* __restrict__ dout) {
    int i = blockIdx.x;
    int w = threadIdx.x >> 5, lane = threadIdx.x & 31;
    float s = 0.0f;
    for (int d = lane; d < DD; d += 32) s += out[i * DD + d] * Wc[d * 3 + w];
    #pragma unroll
    for (int o = 16; o > 0; o >>= 1) s += __shfl_down_sync(0xFFFFFFFFu, s, o);
    if (lane == 0) dout[(size_t)i * (DD + 3) + DD + w] = s;
}

// ---------------- host launcher ----------------
static void* symaddr(const void* s) {
    void* p = nullptr;
    cudaGetSymbolAddress(&p, s);
    return p;
}

extern "C" void kernel_launch(void* const* d_in, const int* in_sizes, int n_in,
                              void* d_out, int out_size) {
    const float* feat   = (const float*)d_in[0];
    const float* coord  = (const float*)d_in[1];
    const float* mask   = (const float*)d_in[2];
    const float* tptr   = (const float*)d_in[3];
    const float* pos    = (const float*)d_in[4];
    const float* W_in   = (const float*)d_in[5];
    const float* W_self = (const float*)d_in[6];
    const float* W_rad  = (const float*)d_in[7];
    const float* W_conv = (const float*)d_in[8];
    const float* W_cat  = (const float*)d_in[9];
    const float* W_out  = (const float*)d_in[10];
    const float* W_noise= (const float*)d_in[11];
    const float* W_coord= (const float*)d_in[12];
    float* out = (float*)d_out;

    float* p_inh  = (float*)symaddr(g_inh);
    float* p_inl  = (float*)symaddr(g_inl);
    float* p_cath = (float*)symaddr(g_cath);
    float* p_catl = (float*)symaddr(g_catl);
    float* p_hs   = (float*)symaddr(g_hs);
    float* p_msgh = (float*)symaddr(g_msgh);
    float* p_msgl = (float*)symaddr(g_msgl);
    float* p_sth  = (float*)symaddr(g_sth);
    float* p_stl  = (float*)symaddr(g_stl);
    float* p_out  = (float*)symaddr(g_out);
    float* p_outh = (float*)symaddr(g_outh);
    float* p_outl = (float*)symaddr(g_outl);
    int*   p_idx  = (int*)symaddr(g_idx);
    float* p_ed   = (float*)symaddr(g_ed);
    float* p_rbfh = (float*)symaddr(g_rbfh);
    float* p_rbfl = (float*)symaddr(g_rbfl);
    float* p_sx   = (float*)symaddr(g_sx);
    float* p_sy   = (float*)symaddr(g_sy);
    float* p_sz   = (float*)symaddr(g_sz);
    float* p_whi  = (float*)symaddr(g_whi);
    float* p_wlo  = (float*)symaddr(g_wlo);

    cudaFuncSetAttribute(msg_mma_kernel, cudaFuncAttributeMaxDynamicSharedMemorySize,
                         MSG_SMEM);

    // ---- weight split prologue ----
    auto spl = [&](const float* src, int off, int n, int nsrc) {
        splitw_kernel<<<(n + 255) / 256, 256>>>(src, p_whi + off, p_wlo + off, n, nsrc);
    };
    spl(W_in,    OFF_WIN,    SZ_WIN,    CIN * DD);
    spl(W_self,  OFF_WSELF,  SZ_WSELF,  SZ_WSELF);
    spl(W_conv,  OFF_WCONV,  SZ_WCONV,  SZ_WCONV);
    spl(W_cat,   OFF_WCAT,   SZ_WCAT,   SZ_WCAT);
    spl(W_out,   OFF_WOUT,   SZ_WOUT,   SZ_WOUT);
    spl(W_noise, OFF_WNOISE, SZ_WNOISE, SZ_WNOISE);
    spl(W_rad,   OFF_WRAD,   SZ_WRAD,   SZ_WRAD);

    int gg = NN / 32;   // 128 blocks

    build_in_kernel<<<NN, 128>>>(feat, pos, mask, tptr, p_inh, p_inl);
    // h = LN(in @ W_in) * mask -> cat[:, :256] hi/lo + states col 0
    gemm_ln_kernel<true><<<gg, 256>>>(p_inh, p_inl, CINP,
                                      p_whi + OFF_WIN, p_wlo + OFF_WIN, CINP,
                                      nullptr, 0, p_cath, p_catl, 2 * DD,
                                      p_sth, p_stl, 0, mask);
    soa_kernel<<<NN / 256, 256>>>(coord, p_sx, p_sy, p_sz);
    knn_kernel<<<NN, 256>>>(p_sx, p_sy, p_sz, p_idx, p_ed);
    rbf_kernel<<<(NN * KK * BB + 255) / 256, 256>>>(p_ed, p_rbfh, p_rbfl);

    for (int l = 0; l < LL; l++) {
        const float* wsh = p_whi + OFF_WSELF + (size_t)l * DD * DD;
        const float* wsl = p_wlo + OFF_WSELF + (size_t)l * DD * DD;
        const float* wch = p_whi + OFF_WCONV + (size_t)l * DD * DD;
        const float* wcl = p_wlo + OFF_WCONV + (size_t)l * DD * DD;
        const float* wth = p_whi + OFF_WCAT + (size_t)l * 2 * DD * DD;
        const float* wtl = p_wlo + OFF_WCAT + (size_t)l * 2 * DD * DD;
        const float* wrh = p_whi + OFF_WRAD + (size_t)l * BB * DD;
        const float* wrl = p_wlo + OFF_WRAD + (size_t)l * BB * DD;

        // hs = LN(h @ W_self[l])  (fp32 only, for the gather)
        gemm_ln_kernel<true><<<gg, 256>>>(p_cath, p_catl, 2 * DD, wsh, wsl, DD,
                                          p_hs, DD, nullptr, nullptr, 0,
                                          nullptr, nullptr, 0, nullptr);
        // msg = mean_k( hs[idx] * (rbf @ W_rad[l]) )  -> pre-split
        msg_mma_kernel<<<NN, 256, MSG_SMEM>>>(p_hs, p_idx, p_rbfh, p_rbfl,
                                              wrh, wrl, p_msgh, p_msgl);
        // agg = msg @ W_conv[l] -> cat[:, 256:512] hi/lo
        gemm_ln_kernel<false><<<gg, 256>>>(p_msgh, p_msgl, DD, wch, wcl, DD,
                                           nullptr, 0, p_cath + DD, p_catl + DD, 2 * DD,
                                           nullptr, nullptr, 0, nullptr);
        // h = LN([h|agg] @ W_cat[l]) * mask -> cat[:, :256] hi/lo (in-place) + states
        gemm_ln_kernel<true><<<gg, 256>>>(p_cath, p_catl, 2 * DD, wth, wtl, 2 * DD,
                                          nullptr, 0, p_cath, p_catl, 2 * DD,
                                          p_sth, p_stl, l + 1, mask);
    }

    // out = states @ W_out  (fp32 for coord head + split for noise head)
    gemm_ln_kernel<false><<<gg, 256>>>(p_sth, p_stl, NSTATE * DD,
                                       p_whi + OFF_WOUT, p_wlo + OFF_WOUT, NSTATE * DD,
                                       p_out, DD, p_outh, p_outl, DD,
                                       nullptr, nullptr, 0, nullptr);
    // d_out[:, :256] = out @ W_noise  (ldc 259)
    gemm_ln_kernel<false><<<gg, 256>>>(p_outh, p_outl, DD,
                                       p_whi + OFF_WNOISE, p_wlo + OFF_WNOISE, DD,
                                       out, DD + 3, nullptr, nullptr, 0,
                                       nullptr, nullptr, 0, nullptr);
    // d_out[:, 256:259] = out @ W_coord
    coord_out_kernel<<<NN, 96>>>(p_out, W_coord, out);
}

// round 7
// speedup vs baseline: 1.1845x; 1.1845x over previous
#include <cuda_runtime.h>
#include <math.h>

#define NN 4096
#define DD 256
#define KK 32
#define LL 4
#define TT 100
#define PP 64
#define BB 32
#define CIN 420
#define NSTATE 5

// ---------------- scratch (device globals; no allocations) ----------------
__device__ float g_in[NN * CIN];
__device__ float g_cat[NN * 2 * DD];     // [h | agg] (ld 512)
__device__ float g_hs[NN * DD];
__device__ float g_msg[NN * DD];
__device__ float g_states[NN * NSTATE * DD];
__device__ float g_out[NN * DD];
__device__ int   g_idx[NN * KK];
__device__ float g_ed[NN * KK];
__device__ float g_rbf[NN * KK * BB];
__device__ float g_sx[NN], g_sy[NN], g_sz[NN];

// ---------------- helpers ----------------
__device__ __forceinline__ float f2tf(float x) {
    unsigned r;
    asm("cvt.rna.tf32.f32 %0, %1;" : "=r"(r) : "f"(x));
    return __uint_as_float(r);
}
__device__ __forceinline__ void split2(float f, unsigned& hi, unsigned& lo) {
    float h = f2tf(f);
    float l = f2tf(f - h);
    hi = __float_as_uint(h);
    lo = __float_as_uint(l);
}
__device__ __forceinline__ void split2f(float f, float& hi, float& lo) {
    hi = f2tf(f);
    lo = f2tf(f - hi);
}
__device__ __forceinline__ void mma_tf32(float& d0, float& d1, float& d2, float& d3,
                                         unsigned a0, unsigned a1, unsigned a2, unsigned a3,
                                         unsigned b0, unsigned b1) {
    asm volatile(
        "mma.sync.aligned.m16n8k8.row.col.f32.tf32.tf32.f32 "
        "{%0,%1,%2,%3}, {%4,%5,%6,%7}, {%8,%9}, {%0,%1,%2,%3};"
        : "+f"(d0), "+f"(d1), "+f"(d2), "+f"(d3)
        : "r"(a0), "r"(a1), "r"(a2), "r"(a3), "r"(b0), "r"(b1));
}

// ---------------- input build ----------------
__global__ void build_in_kernel(const float* __restrict__ feat,
                                const float* __restrict__ pos,
                                const float* __restrict__ mask,
                                const float* __restrict__ tptr,
                                float* __restrict__ out) {
    int i = blockIdx.x;
    float t = *tptr;
    float mk = mask[i];
    for (int c = threadIdx.x; c < CIN; c += blockDim.x) {
        float v;
        if (c < TT) {
            float d = (t - (float)c * (1.0f / 99.0f)) * 99.0f;
            float a = fabsf(d);
            if (a < 1.0f) {
                float cc = cospif(0.5f * d);
                v = cc * cc * mk;
            } else v = 0.0f;
        } else if (c < TT + DD) {
            v = feat[i * DD + (c - TT)];
        } else {
            v = pos[i * PP + (c - TT - DD)];
        }
        out[i * CIN + c] = v;
    }
}

// ---------------- SoA coord transpose ----------------
__global__ void soa_kernel(const float* __restrict__ coord,
                           float* __restrict__ gx, float* __restrict__ gy,
                           float* __restrict__ gz) {
    int j = blockIdx.x * 256 + threadIdx.x;
    if (j < NN) {
        gx[j] = coord[j * 3 + 0];
        gy[j] = coord[j * 3 + 1];
        gz[j] = coord[j * 3 + 2];
    }
}

// ---------------- kNN: register distances, lazy re-reduce ----------------
__global__ __launch_bounds__(256) void knn_kernel(const float* __restrict__ gx,
                                                  const float* __restrict__ gy,
                                                  const float* __restrict__ gz,
                                                  int* __restrict__ idx_out,
                                                  float* __restrict__ ed_out) {
    __shared__ float wv[8];
    __shared__ int wi[8];
    __shared__ int s_sel;
    int i = blockIdx.x;
    int tid = threadIdx.x;
    int lane = tid & 31;
    int warp = tid >> 5;
    float cx = gx[i], cy = gy[i], cz = gz[i];
    float d2r[16];
    unsigned exm = 0;
    float v = 3.4e38f;
    int bi = 0x7FFFFFFF;
    #pragma unroll
    for (int s = 0; s < 16; s++) {
        int j = tid + s * 256;
        float dx = cx - gx[j];
        float dy = cy - gy[j];
        float dz = cz - gz[j];
        float d2 = dx * dx + dy * dy + dz * dz;
        if (j == i) d2 += 1e9f;
        d2r[s] = d2;
        if (d2 < v) { v = d2; bi = j; }
    }
    {
        float rv = v; int rb = bi;
        #pragma unroll
        for (int o = 16; o > 0; o >>= 1) {
            float ov = __shfl_down_sync(0xFFFFFFFFu, rv, o);
            int ob = __shfl_down_sync(0xFFFFFFFFu, rb, o);
            if (ov < rv || (ov == rv && ob < rb)) { rv = ov; rb = ob; }
        }
        if (lane == 0) { wv[warp] = rv; wi[warp] = rb; }
    }
    __syncthreads();
    for (int kk = 0; kk < KK; kk++) {
        if (warp == 0) {
            float v2 = (lane < 8) ? wv[lane] : 3.4e38f;
            int b2 = (lane < 8) ? wi[lane] : 0x7FFFFFFF;
            #pragma unroll
            for (int o = 4; o > 0; o >>= 1) {
                float ov = __shfl_down_sync(0xFFFFFFFFu, v2, o);
                int ob = __shfl_down_sync(0xFFFFFFFFu, b2, o);
                if (ov < v2 || (ov == v2 && ob < b2)) { v2 = ov; b2 = ob; }
            }
            if (lane == 0) {
                idx_out[i * KK + kk] = b2;
                ed_out[i * KK + kk] = sqrtf(fmaxf(v2, 1e-12f));
                s_sel = b2;
            }
        }
        __syncthreads();
        int b = s_sel;
        int owner = b & 255;
        if (tid == owner) {
            exm |= 1u << ((b - tid) >> 8);
            v = 3.4e38f; bi = 0x7FFFFFFF;
            #pragma unroll
            for (int s = 0; s < 16; s++) {
                float d2 = d2r[s];
                bool live = ((exm >> s) & 1u) == 0u;
                if (live && d2 < v) { v = d2; bi = tid + s * 256; }
            }
        }
        if (kk + 1 < KK && warp == (owner >> 5)) {
            float rv = v; int rb = bi;
            #pragma unroll
            for (int o = 16; o > 0; o >>= 1) {
                float ov = __shfl_down_sync(0xFFFFFFFFu, rv, o);
                int ob = __shfl_down_sync(0xFFFFFFFFu, rb, o);
                if (ov < rv || (ov == rv && ob < rb)) { rv = ov; rb = ob; }
            }
            if (lane == 0) { wv[warp] = rv; wi[warp] = rb; }
        }
        __syncthreads();
    }
}

// ---------------- gaussian RBF ----------------
__global__ void rbf_kernel(const float* __restrict__ ed, float* __restrict__ rbf) {
    int t = blockIdx.x * blockDim.x + threadIdx.x;
    if (t >= NN * KK * BB) return;
    int b = t & (BB - 1);
    int ik = t >> 5;
    float d = ed[ik];
    float c = 32.0f * (float)b * (1.0f / 31.0f);
    float x = d - c;
    rbf[t] = expf(-x * x);
}

// ================= split-tf32 GEMM(+LN): A pre-split in smem =================
// Block tile 32x256 (full rows), BK=32, 8 warps, warp tile 32x32.
#define GBK 32
#define AST 36
#define BST 264

template <bool DO_LN>
__global__ __launch_bounds__(256) void gemm_ln_kernel(const float* __restrict__ A,
                                                      const float* __restrict__ Bm,
                                                      float* __restrict__ C,
                                                      int Kd, int lda, int ldc,
                                                      const float* __restrict__ mask,
                                                      float* __restrict__ states,
                                                      int state_col) {
    __shared__ float Ash[32 * AST];
    __shared__ float Asl[32 * AST];
    __shared__ float Bs[32 * BST];
    int tid = threadIdx.x;
    int bm = blockIdx.x * 32;
    int warp = tid >> 5, lane = tid & 31;
    int gid = lane >> 2, tig = lane & 3;

    const float* Abase = A + (size_t)bm * lda;

    float4 avr;
    float4 bvr[8];
    int ar = tid >> 3;
    int ac4 = (tid & 7) * 4;

    auto load_tile = [&](int k0) {
        const float* p = Abase + (size_t)ar * lda + k0 + ac4;
        if (k0 + ac4 + 4 <= Kd) {
            avr = *reinterpret_cast<const float4*>(p);
        } else {
            float x0 = (k0 + ac4 + 0 < Kd) ? p[0] : 0.0f;
            float x1 = (k0 + ac4 + 1 < Kd) ? p[1] : 0.0f;
            float x2 = (k0 + ac4 + 2 < Kd) ? p[2] : 0.0f;
            float x3 = (k0 + ac4 + 3 < Kd) ? p[3] : 0.0f;
            avr = make_float4(x0, x1, x2, x3);
        }
        #pragma unroll
        for (int it = 0; it < 8; it++) {
            int idx = it * 256 + tid;
            int r = idx >> 6;
            int c4 = (idx & 63) * 4;
            if (k0 + r < Kd) {
                bvr[it] = *reinterpret_cast<const float4*>(Bm + (size_t)(k0 + r) * DD + c4);
            } else {
                bvr[it] = make_float4(0.f, 0.f, 0.f, 0.f);
            }
        }
    };
    auto store_tile = [&]() {
        float4 hi, lo;
        split2f(avr.x, hi.x, lo.x);
        split2f(avr.y, hi.y, lo.y);
        split2f(avr.z, hi.z, lo.z);
        split2f(avr.w, hi.w, lo.w);
        *reinterpret_cast<float4*>(&Ash[ar * AST + ac4]) = hi;
        *reinterpret_cast<float4*>(&Asl[ar * AST + ac4]) = lo;
        #pragma unroll
        for (int it = 0; it < 8; it++) {
            int idx = it * 256 + tid;
            int r = idx >> 6;
            int c4 = (idx & 63) * 4;
            *reinterpret_cast<float4*>(&Bs[r * BST + c4]) = bvr[it];
        }
    };

    float cf[2][4][4];
    #pragma unroll
    for (int mt = 0; mt < 2; mt++)
        #pragma unroll
        for (int nt = 0; nt < 4; nt++)
            #pragma unroll
            for (int q = 0; q < 4; q++) cf[mt][nt][q] = 0.0f;

    load_tile(0);
    store_tile();
    __syncthreads();

    for (int k0 = 0;;) {
        int knext = k0 + GBK;
        bool has_next = knext < Kd;
        if (has_next) load_tile(knext);
        #pragma unroll
        for (int ks = 0; ks < 4; ks++) {
            int kc = ks * 8 + tig;
            unsigned ah[2][4], al[2][4];
            #pragma unroll
            for (int mt = 0; mt < 2; mt++) {
                int r = gid + mt * 16;
                ah[mt][0] = __float_as_uint(Ash[r * AST + kc]);
                ah[mt][1] = __float_as_uint(Ash[(r + 8) * AST + kc]);
                ah[mt][2] = __float_as_uint(Ash[r * AST + kc + 4]);
                ah[mt][3] = __float_as_uint(Ash[(r + 8) * AST + kc + 4]);
                al[mt][0] = __float_as_uint(Asl[r * AST + kc]);
                al[mt][1] = __float_as_uint(Asl[(r + 8) * AST + kc]);
                al[mt][2] = __float_as_uint(Asl[r * AST + kc + 4]);
                al[mt][3] = __float_as_uint(Asl[(r + 8) * AST + kc + 4]);
            }
            unsigned bh[4][2], bl[4][2];
            #pragma unroll
            for (int nt = 0; nt < 4; nt++) {
                int cb = warp * 32 + nt * 8 + gid;
                split2(Bs[(ks * 8 + tig) * BST + cb],     bh[nt][0], bl[nt][0]);
                split2(Bs[(ks * 8 + tig + 4) * BST + cb], bh[nt][1], bl[nt][1]);
            }
            #pragma unroll
            for (int mt = 0; mt < 2; mt++)
                #pragma unroll
                for (int nt = 0; nt < 4; nt++) {
                    mma_tf32(cf[mt][nt][0], cf[mt][nt][1], cf[mt][nt][2], cf[mt][nt][3],
                             ah[mt][0], ah[mt][1], ah[mt][2], ah[mt][3],
                             bh[nt][0], bh[nt][1]);
                    mma_tf32(cf[mt][nt][0], cf[mt][nt][1], cf[mt][nt][2], cf[mt][nt][3],
                             ah[mt][0], ah[mt][1], ah[mt][2], ah[mt][3],
                             bl[nt][0], bl[nt][1]);
                    mma_tf32(cf[mt][nt][0], cf[mt][nt][1], cf[mt][nt][2], cf[mt][nt][3],
                             al[mt][0], al[mt][1], al[mt][2], al[mt][3],
                             bh[nt][0], bh[nt][1]);
                }
        }
        if (!has_next) break;
        __syncthreads();
        store_tile();
        __syncthreads();
        k0 = knext;
    }

    if (!DO_LN) {
        if ((ldc & 1) == 0) {
            #pragma unroll
            for (int mt = 0; mt < 2; mt++)
                #pragma unroll
                for (int nt = 0; nt < 4; nt++) {
                    int r0 = bm + gid + mt * 16;
                    int c = warp * 32 + nt * 8 + tig * 2;
                    *reinterpret_cast<float2*>(C + (size_t)r0 * ldc + c) =
                        make_float2(cf[mt][nt][0], cf[mt][nt][1]);
                    *reinterpret_cast<float2*>(C + (size_t)(r0 + 8) * ldc + c) =
                        make_float2(cf[mt][nt][2], cf[mt][nt][3]);
                }
        } else {
            #pragma unroll
            for (int mt = 0; mt < 2; mt++)
                #pragma unroll
                for (int nt = 0; nt < 4; nt++) {
                    int r0 = bm + gid + mt * 16;
                    int c = warp * 32 + nt * 8 + tig * 2;
                    C[(size_t)r0 * ldc + c]           = cf[mt][nt][0];
                    C[(size_t)r0 * ldc + c + 1]       = cf[mt][nt][1];
                    C[(size_t)(r0 + 8) * ldc + c]     = cf[mt][nt][2];
                    C[(size_t)(r0 + 8) * ldc + c + 1] = cf[mt][nt][3];
                }
        }
        return;
    }

    // ---- LN epilogue: stage in Bs ----
    __syncthreads();
    #pragma unroll
    for (int mt = 0; mt < 2; mt++)
        #pragma unroll
        for (int nt = 0; nt < 4; nt++) {
            int r = gid + mt * 16;
            int c = warp * 32 + nt * 8 + tig * 2;
            Bs[r * BST + c]           = cf[mt][nt][0];
            Bs[r * BST + c + 1]       = cf[mt][nt][1];
            Bs[(r + 8) * BST + c]     = cf[mt][nt][2];
            Bs[(r + 8) * BST + c + 1] = cf[mt][nt][3];
        }
    __syncthreads();

    int row = tid >> 3;
    int sub = tid & 7;
    float s = 0.0f, s2 = 0.0f;
    #pragma unroll
    for (int j = 0; j < 32; j++) {
        float x = Bs[row * BST + sub + j * 8];
        s += x;
        s2 += x * x;
    }
    #pragma unroll
    for (int o = 4; o > 0; o >>= 1) {
        s  += __shfl_xor_sync(0xFFFFFFFFu, s, o);
        s2 += __shfl_xor_sync(0xFFFFFFFFu, s2, o);
    }
    float mean = s * (1.0f / DD);
    float var = s2 * (1.0f / DD) - mean * mean;
    float scale = rsqrtf(var + 1e-5f);
    int i = bm + row;
    float mk = mask ? mask[i] : 1.0f;
    float* yrow = C + (size_t)i * ldc;
    float* srow = states ? states + (size_t)i * (NSTATE * DD) + state_col * DD : nullptr;
    #pragma unroll
    for (int j = 0; j < 32; j++) {
        int c = sub + j * 8;
        float y = (Bs[row * BST + c] - mean) * scale * mk;
        yrow[c] = y;
        if (srow) srow[c] = y;
    }
}

// ================= tensor-core message kernel (A pre-split in smem) =================
__global__ __launch_bounds__(256) void msg_mma_kernel(const float* __restrict__ h,
                                                      const int* __restrict__ idx,
                                                      const float* __restrict__ rbf,
                                                      const float* __restrict__ Wrad,
                                                      float* __restrict__ out) {
    __shared__ float Ash[32 * AST];
    __shared__ float Asl[32 * AST];
    __shared__ float Bs[32 * BST];
    __shared__ int js[KK];
    int i = blockIdx.x;
    int tid = threadIdx.x;
    int warp = tid >> 5, lane = tid & 31;
    int gid = lane >> 2, tig = lane & 3;

    {
        int r = tid >> 3;
        int b4 = (tid & 7) * 4;
        float4 v = *reinterpret_cast<const float4*>(rbf + (size_t)i * (KK * BB) + r * BB + b4);
        float4 hi, lo;
        split2f(v.x, hi.x, lo.x);
        split2f(v.y, hi.y, lo.y);
        split2f(v.z, hi.z, lo.z);
        split2f(v.w, hi.w, lo.w);
        *reinterpret_cast<float4*>(&Ash[r * AST + b4]) = hi;
        *reinterpret_cast<float4*>(&Asl[r * AST + b4]) = lo;
    }
    #pragma unroll
    for (int it = 0; it < 8; it++) {
        int idx2 = it * 256 + tid;
        int r = idx2 >> 6;
        int c4 = (idx2 & 63) * 4;
        *reinterpret_cast<float4*>(&Bs[r * BST + c4]) =
            *reinterpret_cast<const float4*>(Wrad + (size_t)r * DD + c4);
    }
    if (tid < KK) js[tid] = idx[i * KK + tid];
    __syncthreads();

    float cf[2][4][4];
    #pragma unroll
    for (int mt = 0; mt < 2; mt++)
        #pragma unroll
        for (int nt = 0; nt < 4; nt++)
            #pragma unroll
            for (int q = 0; q < 4; q++) cf[mt][nt][q] = 0.0f;

    #pragma unroll
    for (int ks = 0; ks < 4; ks++) {
        int kc = ks * 8 + tig;
        unsigned ah[2][4], al[2][4];
        #pragma unroll
        for (int mt = 0; mt < 2; mt++) {
            int r = gid + mt * 16;
            ah[mt][0] = __float_as_uint(Ash[r * AST + kc]);
            ah[mt][1] = __float_as_uint(Ash[(r + 8) * AST + kc]);
            ah[mt][2] = __float_as_uint(Ash[r * AST + kc + 4]);
            ah[mt][3] = __float_as_uint(Ash[(r + 8) * AST + kc + 4]);
            al[mt][0] = __float_as_uint(Asl[r * AST + kc]);
            al[mt][1] = __float_as_uint(Asl[(r + 8) * AST + kc]);
            al[mt][2] = __float_as_uint(Asl[r * AST + kc + 4]);
            al[mt][3] = __float_as_uint(Asl[(r + 8) * AST + kc + 4]);
        }
        unsigned bh[4][2], bl[4][2];
        #pragma unroll
        for (int nt = 0; nt < 4; nt++) {
            int cb = warp * 32 + nt * 8 + gid;
            split2(Bs[(ks * 8 + tig) * BST + cb],     bh[nt][0], bl[nt][0]);
            split2(Bs[(ks * 8 + tig + 4) * BST + cb], bh[nt][1], bl[nt][1]);
        }
        #pragma unroll
        for (int mt = 0; mt < 2; mt++)
            #pragma unroll
            for (int nt = 0; nt < 4; nt++) {
                mma_tf32(cf[mt][nt][0], cf[mt][nt][1], cf[mt][nt][2], cf[mt][nt][3],
                         ah[mt][0], ah[mt][1], ah[mt][2], ah[mt][3],
                         bh[nt][0], bh[nt][1]);
                mma_tf32(cf[mt][nt][0], cf[mt][nt][1], cf[mt][nt][2], cf[mt][nt][3],
                         ah[mt][0], ah[mt][1], ah[mt][2], ah[mt][3],
                         bl[nt][0], bl[nt][1]);
                mma_tf32(cf[mt][nt][0], cf[mt][nt][1], cf[mt][nt][2], cf[mt][nt][3],
                         al[mt][0], al[mt][1], al[mt][2], al[mt][3],
                         bh[nt][0], bh[nt][1]);
            }
    }
    __syncthreads();

    // gather H rows into Bs
    #pragma unroll
    for (int it = 0; it < 8; it++) {
        int idx2 = it * 256 + tid;
        int r = idx2 >> 6;
        int c4 = (idx2 & 63) * 4;
        int j = js[r];
        *reinterpret_cast<float4*>(&Bs[r * BST + c4]) =
            *reinterpret_cast<const float4*>(h + (size_t)j * DD + c4);
    }
    __syncthreads();

    float sacc[4][2];
    #pragma unroll
    for (int nt = 0; nt < 4; nt++) { sacc[nt][0] = 0.0f; sacc[nt][1] = 0.0f; }
    #pragma unroll
    for (int mt = 0; mt < 2; mt++) {
        int r = gid + mt * 16;
        #pragma unroll
        for (int nt = 0; nt < 4; nt++) {
            int c = warp * 32 + nt * 8 + tig * 2;
            sacc[nt][0] += cf[mt][nt][0] * Bs[r * BST + c];
            sacc[nt][1] += cf[mt][nt][1] * Bs[r * BST + c + 1];
            sacc[nt][0] += cf[mt][nt][2] * Bs[(r + 8) * BST + c];
            sacc[nt][1] += cf[mt][nt][3] * Bs[(r + 8) * BST + c + 1];
        }
    }
    #pragma unroll
    for (int o = 4; o <= 16; o <<= 1) {
        #pragma unroll
        for (int nt = 0; nt < 4; nt++) {
            sacc[nt][0] += __shfl_xor_sync(0xFFFFFFFFu, sacc[nt][0], o);
            sacc[nt][1] += __shfl_xor_sync(0xFFFFFFFFu, sacc[nt][1], o);
        }
    }
    if (gid == 0) {
        #pragma unroll
        for (int nt = 0; nt < 4; nt++) {
            int c = warp * 32 + nt * 8 + tig * 2;
            out[(size_t)i * DD + c]     = sacc[nt][0] * (1.0f / KK);
            out[(size_t)i * DD + c + 1] = sacc[nt][1] * (1.0f / KK);
        }
    }
}

// ---------------- coord head ----------------
__global__ void coord_out_kernel(const float* __restrict__ out,
                                 const float* __restrict__ Wc,
                                 float* __restrict__ dout) {
    int i = blockIdx.x;
    int w = threadIdx.x >> 5, lane = threadIdx.x & 31;
    float s = 0.0f;
    for (int d = lane; d < DD; d += 32) s += out[i * DD + d] * Wc[d * 3 + w];
    #pragma unroll
    for (int o = 16; o > 0; o >>= 1) s += __shfl_down_sync(0xFFFFFFFFu, s, o);
    if (lane == 0) dout[(size_t)i * (DD + 3) + DD + w] = s;
}

// ---------------- host launcher ----------------
static void* symaddr(const void* s) {
    void* p = nullptr;
    cudaGetSymbolAddress(&p, s);
    return p;
}

extern "C" void kernel_launch(void* const* d_in, const int* in_sizes, int n_in,
                              void* d_out, int out_size) {
    const float* feat   = (const float*)d_in[0];
    const float* coord  = (const float*)d_in[1];
    const float* mask   = (const float*)d_in[2];
    const float* tptr   = (const float*)d_in[3];
    const float* pos    = (const float*)d_in[4];
    const float* W_in   = (const float*)d_in[5];
    const float* W_self = (const float*)d_in[6];
    const float* W_rad  = (const float*)d_in[7];
    const float* W_conv = (const float*)d_in[8];
    const float* W_cat  = (const float*)d_in[9];
    const float* W_out  = (const float*)d_in[10];
    const float* W_noise= (const float*)d_in[11];
    const float* W_coord= (const float*)d_in[12];
    float* out = (float*)d_out;

    float* p_in     = (float*)symaddr(g_in);
    float* p_cat    = (float*)symaddr(g_cat);
    float* p_hs     = (float*)symaddr(g_hs);
    float* p_msg    = (float*)symaddr(g_msg);
    float* p_states = (float*)symaddr(g_states);
    float* p_out    = (float*)symaddr(g_out);
    int*   p_idx    = (int*)symaddr(g_idx);
    float* p_ed     = (float*)symaddr(g_ed);
    float* p_rbf    = (float*)symaddr(g_rbf);
    float* p_sx     = (float*)symaddr(g_sx);
    float* p_sy     = (float*)symaddr(g_sy);
    float* p_sz     = (float*)symaddr(g_sz);

    int gg = NN / 32;   // 128 blocks

    build_in_kernel<<<NN, 128>>>(feat, pos, mask, tptr, p_in);
    gemm_ln_kernel<true><<<gg, 256>>>(p_in, W_in, p_cat, CIN, CIN, 2 * DD,
                                      mask, p_states, 0);
    soa_kernel<<<NN / 256, 256>>>(coord, p_sx, p_sy, p_sz);
    knn_kernel<<<NN, 256>>>(p_sx, p_sy, p_sz, p_idx, p_ed);
    rbf_kernel<<<(NN * KK * BB + 255) / 256, 256>>>(p_ed, p_rbf);

    for (int l = 0; l < LL; l++) {
        const float* Wself_l = W_self + (size_t)l * DD * DD;
        const float* Wrad_l  = W_rad  + (size_t)l * BB * DD;
        const float* Wconv_l = W_conv + (size_t)l * DD * DD;
        const float* Wcat_l  = W_cat  + (size_t)l * 2 * DD * DD;

        gemm_ln_kernel<true><<<gg, 256>>>(p_cat, Wself_l, p_hs, DD, 2 * DD, DD,
                                          nullptr, nullptr, 0);
        msg_mma_kernel<<<NN, 256>>>(p_hs, p_idx, p_rbf, Wrad_l, p_msg);
        gemm_ln_kernel<false><<<gg, 256>>>(p_msg, Wconv_l, p_cat + DD, DD, DD, 2 * DD,
                                           nullptr, nullptr, 0);
        gemm_ln_kernel<true><<<gg, 256>>>(p_cat, Wcat_l, p_cat, 2 * DD, 2 * DD, 2 * DD,
                                          mask, p_states, l + 1);
    }

    gemm_ln_kernel<false><<<gg, 256>>>(p_states, W_out, p_out, NSTATE * DD, NSTATE * DD, DD,
                                       nullptr, nullptr, 0);
    gemm_ln_kernel<false><<<gg, 256>>>(p_out, W_noise, out, DD, DD, DD + 3,
                                       nullptr, nullptr, 0);
    coord_out_kernel<<<NN, 96>>>(p_out, W_coord, out);
}

// round 8
// speedup vs baseline: 1.2112x; 1.0226x over previous
#include <cuda_runtime.h>
#include <math.h>

#define NN 4096
#define DD 256
#define KK 32
#define LL 4
#define TT 100
#define PP 64
#define BB 32
#define CIN 420
#define NSTATE 5

// ---------------- scratch (device globals; no allocations) ----------------
__device__ float g_in[NN * CIN];
__device__ float g_cat[NN * 2 * DD];     // [h | agg] (ld 512)
__device__ float g_hs[NN * DD];
__device__ float g_msg[NN * DD];
__device__ float g_states[NN * NSTATE * DD];
__device__ float g_out[NN * DD];
__device__ int   g_idx[NN * KK];
__device__ float g_ed[NN * KK];
__device__ float g_rbf[NN * KK * BB];
__device__ float g_sx[NN], g_sy[NN], g_sz[NN];

// ---------------- helpers ----------------
__device__ __forceinline__ float f2tf(float x) {
    unsigned r;
    asm("cvt.rna.tf32.f32 %0, %1;" : "=r"(r) : "f"(x));
    return __uint_as_float(r);
}
__device__ __forceinline__ void split2(float f, unsigned& hi, unsigned& lo) {
    float h = f2tf(f);
    float l = f2tf(f - h);
    hi = __float_as_uint(h);
    lo = __float_as_uint(l);
}
__device__ __forceinline__ void split2f(float f, float& hi, float& lo) {
    hi = f2tf(f);
    lo = f2tf(f - hi);
}
__device__ __forceinline__ void mma_tf32(float& d0, float& d1, float& d2, float& d3,
                                         unsigned a0, unsigned a1, unsigned a2, unsigned a3,
                                         unsigned b0, unsigned b1) {
    asm volatile(
        "mma.sync.aligned.m16n8k8.row.col.f32.tf32.tf32.f32 "
        "{%0,%1,%2,%3}, {%4,%5,%6,%7}, {%8,%9}, {%0,%1,%2,%3};"
        : "+f"(d0), "+f"(d1), "+f"(d2), "+f"(d3)
        : "r"(a0), "r"(a1), "r"(a2), "r"(a3), "r"(b0), "r"(b1));
}
__device__ __forceinline__ void gbar(int id) {
    asm volatile("bar.sync %0, 256;" :: "r"(id) : "memory");
}

// ---------------- input build ----------------
__global__ void build_in_kernel(const float* __restrict__ feat,
                                const float* __restrict__ pos,
                                const float* __restrict__ mask,
                                const float* __restrict__ tptr,
                                float* __restrict__ out) {
    int i = blockIdx.x;
    float t = *tptr;
    float mk = mask[i];
    for (int c = threadIdx.x; c < CIN; c += blockDim.x) {
        float v;
        if (c < TT) {
            float d = (t - (float)c * (1.0f / 99.0f)) * 99.0f;
            float a = fabsf(d);
            if (a < 1.0f) {
                float cc = cospif(0.5f * d);
                v = cc * cc * mk;
            } else v = 0.0f;
        } else if (c < TT + DD) {
            v = feat[i * DD + (c - TT)];
        } else {
            v = pos[i * PP + (c - TT - DD)];
        }
        out[i * CIN + c] = v;
    }
}

// ---------------- SoA coord transpose ----------------
__global__ void soa_kernel(const float* __restrict__ coord,
                           float* __restrict__ gx, float* __restrict__ gy,
                           float* __restrict__ gz) {
    int j = blockIdx.x * 256 + threadIdx.x;
    if (j < NN) {
        gx[j] = coord[j * 3 + 0];
        gy[j] = coord[j * 3 + 1];
        gz[j] = coord[j * 3 + 2];
    }
}

// ---------------- kNN (R5 smem version: occ 90%) ----------------
__global__ __launch_bounds__(256) void knn_kernel(const float* __restrict__ gx,
                                                  const float* __restrict__ gy,
                                                  const float* __restrict__ gz,
                                                  int* __restrict__ idx_out,
                                                  float* __restrict__ ed_out) {
    __shared__ float dist[NN];
    __shared__ float wv[8];
    __shared__ int wi[8];
    __shared__ int s_sel;
    int i = blockIdx.x;
    int tid = threadIdx.x;
    int lane = tid & 31;
    int warp = tid >> 5;
    float cx = gx[i], cy = gy[i], cz = gz[i];
    float v = 3.4e38f;
    int bi = 0x7FFFFFFF;
    for (int j = tid; j < NN; j += 256) {
        float dx = cx - gx[j];
        float dy = cy - gy[j];
        float dz = cz - gz[j];
        float d2 = dx * dx + dy * dy + dz * dz;
        if (j == i) d2 += 1e9f;
        dist[j] = d2;
        if (d2 < v) { v = d2; bi = j; }
    }
    __syncthreads();
    for (int kk = 0; kk < KK; kk++) {
        float rv = v; int rb = bi;
        #pragma unroll
        for (int o = 16; o > 0; o >>= 1) {
            float ov = __shfl_down_sync(0xFFFFFFFFu, rv, o);
            int ob = __shfl_down_sync(0xFFFFFFFFu, rb, o);
            if (ov < rv || (ov == rv && ob < rb)) { rv = ov; rb = ob; }
        }
        if (lane == 0) { wv[warp] = rv; wi[warp] = rb; }
        __syncthreads();
        if (warp == 0) {
            float v2 = (lane < 8) ? wv[lane] : 3.4e38f;
            int b2 = (lane < 8) ? wi[lane] : 0x7FFFFFFF;
            #pragma unroll
            for (int o = 4; o > 0; o >>= 1) {
                float ov = __shfl_down_sync(0xFFFFFFFFu, v2, o);
                int ob = __shfl_down_sync(0xFFFFFFFFu, b2, o);
                if (ov < v2 || (ov == v2 && ob < b2)) { v2 = ov; b2 = ob; }
            }
            if (lane == 0) {
                idx_out[i * KK + kk] = b2;
                ed_out[i * KK + kk] = sqrtf(fmaxf(v2, 1e-12f));
                dist[b2] = 3.4e38f;
                s_sel = b2;
            }
        }
        __syncthreads();
        int b = s_sel;
        if ((b & 255) == tid) {
            v = 3.4e38f; bi = 0x7FFFFFFF;
            for (int j = tid; j < NN; j += 256) {
                float d2 = dist[j];
                if (d2 < v) { v = d2; bi = j; }
            }
        }
    }
}

// ---------------- gaussian RBF ----------------
__global__ void rbf_kernel(const float* __restrict__ ed, float* __restrict__ rbf) {
    int t = blockIdx.x * blockDim.x + threadIdx.x;
    if (t >= NN * KK * BB) return;
    int b = t & (BB - 1);
    int ik = t >> 5;
    float d = ed[ik];
    float c = 32.0f * (float)b * (1.0f / 31.0f);
    float x = d - c;
    rbf[t] = expf(-x * x);
}

// ================= split-tf32 GEMM(+LN), K-split 2 groups x 8 warps =================
// Block tile 32x256 (full rows). 512 threads. Group g computes its K half,
// then partials are summed in smem; optional fused LN.
#define GBK 32
#define AST 36
#define BST 264
#define GRP_FLOATS (2 * 32 * AST + 32 * BST)   // Ash + Asl + Bs per group
#define GEMM_SMEM (2 * GRP_FLOATS * 4)

template <bool DO_LN>
__global__ __launch_bounds__(512) void gemm_ln_kernel(const float* __restrict__ A,
                                                      const float* __restrict__ Bm,
                                                      float* __restrict__ C,
                                                      int Kd, int lda, int ldc,
                                                      const float* __restrict__ mask,
                                                      float* __restrict__ states,
                                                      int state_col) {
    extern __shared__ float smem[];
    int tid = threadIdx.x;
    int grp = tid >> 8;         // 0 or 1
    int t = tid & 255;          // tid within group
    float* Ash = smem + grp * GRP_FLOATS;
    float* Asl = Ash + 32 * AST;
    float* Bs  = Asl + 32 * AST;
    float* stage = smem + 2 * 32 * AST;   // group 0's Bs region

    int bm = blockIdx.x * 32;
    int warp = t >> 5, lane = t & 31;
    int gid = lane >> 2, tig = lane & 3;

    // K range for this group (split point 32-aligned)
    int khalf = ((Kd / 2 + 31) / 32) * 32;
    int kb = grp ? khalf : 0;
    int ke = grp ? Kd : khalf;

    const float* Abase = A + (size_t)bm * lda;

    float4 avr;
    float4 bvr[8];
    int ar = t >> 3;
    int ac4 = (t & 7) * 4;

    auto load_tile = [&](int k0) {
        const float* p = Abase + (size_t)ar * lda + k0 + ac4;
        if (k0 + ac4 + 4 <= ke) {
            avr = *reinterpret_cast<const float4*>(p);
        } else {
            float x0 = (k0 + ac4 + 0 < ke) ? p[0] : 0.0f;
            float x1 = (k0 + ac4 + 1 < ke) ? p[1] : 0.0f;
            float x2 = (k0 + ac4 + 2 < ke) ? p[2] : 0.0f;
            float x3 = (k0 + ac4 + 3 < ke) ? p[3] : 0.0f;
            avr = make_float4(x0, x1, x2, x3);
        }
        #pragma unroll
        for (int it = 0; it < 8; it++) {
            int idx = it * 256 + t;
            int r = idx >> 6;
            int c4 = (idx & 63) * 4;
            if (k0 + r < ke) {
                bvr[it] = *reinterpret_cast<const float4*>(Bm + (size_t)(k0 + r) * DD + c4);
            } else {
                bvr[it] = make_float4(0.f, 0.f, 0.f, 0.f);
            }
        }
    };
    auto store_tile = [&]() {
        float4 hi, lo;
        split2f(avr.x, hi.x, lo.x);
        split2f(avr.y, hi.y, lo.y);
        split2f(avr.z, hi.z, lo.z);
        split2f(avr.w, hi.w, lo.w);
        *reinterpret_cast<float4*>(&Ash[ar * AST + ac4]) = hi;
        *reinterpret_cast<float4*>(&Asl[ar * AST + ac4]) = lo;
        #pragma unroll
        for (int it = 0; it < 8; it++) {
            int idx = it * 256 + t;
            int r = idx >> 6;
            int c4 = (idx & 63) * 4;
            *reinterpret_cast<float4*>(&Bs[r * BST + c4]) = bvr[it];
        }
    };

    float cf[2][4][4];
    #pragma unroll
    for (int mt = 0; mt < 2; mt++)
        #pragma unroll
        for (int nt = 0; nt < 4; nt++)
            #pragma unroll
            for (int q = 0; q < 4; q++) cf[mt][nt][q] = 0.0f;

    load_tile(kb);
    store_tile();
    gbar(grp + 1);

    for (int k0 = kb;;) {
        int knext = k0 + GBK;
        bool has_next = knext < ke;
        if (has_next) load_tile(knext);
        #pragma unroll
        for (int ks = 0; ks < 4; ks++) {
            int kc = ks * 8 + tig;
            unsigned ah[2][4], al[2][4];
            #pragma unroll
            for (int mt = 0; mt < 2; mt++) {
                int r = gid + mt * 16;
                ah[mt][0] = __float_as_uint(Ash[r * AST + kc]);
                ah[mt][1] = __float_as_uint(Ash[(r + 8) * AST + kc]);
                ah[mt][2] = __float_as_uint(Ash[r * AST + kc + 4]);
                ah[mt][3] = __float_as_uint(Ash[(r + 8) * AST + kc + 4]);
                al[mt][0] = __float_as_uint(Asl[r * AST + kc]);
                al[mt][1] = __float_as_uint(Asl[(r + 8) * AST + kc]);
                al[mt][2] = __float_as_uint(Asl[r * AST + kc + 4]);
                al[mt][3] = __float_as_uint(Asl[(r + 8) * AST + kc + 4]);
            }
            unsigned bh[4][2], bl[4][2];
            #pragma unroll
            for (int nt = 0; nt < 4; nt++) {
                int cb = warp * 32 + nt * 8 + gid;
                split2(Bs[(ks * 8 + tig) * BST + cb],     bh[nt][0], bl[nt][0]);
                split2(Bs[(ks * 8 + tig + 4) * BST + cb], bh[nt][1], bl[nt][1]);
            }
            #pragma unroll
            for (int mt = 0; mt < 2; mt++)
                #pragma unroll
                for (int nt = 0; nt < 4; nt++) {
                    mma_tf32(cf[mt][nt][0], cf[mt][nt][1], cf[mt][nt][2], cf[mt][nt][3],
                             ah[mt][0], ah[mt][1], ah[mt][2], ah[mt][3],
                             bh[nt][0], bh[nt][1]);
                    mma_tf32(cf[mt][nt][0], cf[mt][nt][1], cf[mt][nt][2], cf[mt][nt][3],
                             ah[mt][0], ah[mt][1], ah[mt][2], ah[mt][3],
                             bl[nt][0], bl[nt][1]);
                    mma_tf32(cf[mt][nt][0], cf[mt][nt][1], cf[mt][nt][2], cf[mt][nt][3],
                             al[mt][0], al[mt][1], al[mt][2], al[mt][3],
                             bh[nt][0], bh[nt][1]);
                }
        }
        if (!has_next) break;
        gbar(grp + 1);
        store_tile();
        gbar(grp + 1);
        k0 = knext;
    }

    // ---- cross-group reduction into stage (group 0's Bs) ----
    __syncthreads();
    if (grp == 0) {
        #pragma unroll
        for (int mt = 0; mt < 2; mt++)
            #pragma unroll
            for (int nt = 0; nt < 4; nt++) {
                int r = gid + mt * 16;
                int c = warp * 32 + nt * 8 + tig * 2;
                stage[r * BST + c]           = cf[mt][nt][0];
                stage[r * BST + c + 1]       = cf[mt][nt][1];
                stage[(r + 8) * BST + c]     = cf[mt][nt][2];
                stage[(r + 8) * BST + c + 1] = cf[mt][nt][3];
            }
    }
    __syncthreads();
    if (grp == 1) {
        #pragma unroll
        for (int mt = 0; mt < 2; mt++)
            #pragma unroll
            for (int nt = 0; nt < 4; nt++) {
                int r = gid + mt * 16;
                int c = warp * 32 + nt * 8 + tig * 2;
                stage[r * BST + c]           += cf[mt][nt][0];
                stage[r * BST + c + 1]       += cf[mt][nt][1];
                stage[(r + 8) * BST + c]     += cf[mt][nt][2];
                stage[(r + 8) * BST + c + 1] += cf[mt][nt][3];
            }
    }
    __syncthreads();

    if (!DO_LN) {
        // all 512 threads store 32x256 from stage
        #pragma unroll
        for (int e = 0; e < 16; e++) {
            int idx = tid + e * 512;
            int r = idx >> 8;
            int c = idx & 255;
            C[(size_t)(bm + r) * ldc + c] = stage[r * BST + c];
        }
        return;
    }

    // ---- fused LN: 16 threads per row ----
    int row = tid >> 4;          // 0..31
    int sub = tid & 15;          // 0..15
    float s = 0.0f, s2 = 0.0f;
    #pragma unroll
    for (int j = 0; j < 16; j++) {
        float x = stage[row * BST + sub + j * 16];
        s += x;
        s2 += x * x;
    }
    #pragma unroll
    for (int o = 8; o > 0; o >>= 1) {
        s  += __shfl_xor_sync(0xFFFFFFFFu, s, o);
        s2 += __shfl_xor_sync(0xFFFFFFFFu, s2, o);
    }
    float mean = s * (1.0f / DD);
    float var = s2 * (1.0f / DD) - mean * mean;
    float scale = rsqrtf(var + 1e-5f);
    int i = bm + row;
    float mk = mask ? mask[i] : 1.0f;
    float* yrow = C + (size_t)i * ldc;
    float* srow = states ? states + (size_t)i * (NSTATE * DD) + state_col * DD : nullptr;
    #pragma unroll
    for (int j = 0; j < 16; j++) {
        int c = sub + j * 16;
        float y = (stage[row * BST + c] - mean) * scale * mk;
        yrow[c] = y;
        if (srow) srow[c] = y;
    }
}

// ================= tensor-core message kernel (A pre-split in smem) =================
__global__ __launch_bounds__(256) void msg_mma_kernel(const float* __restrict__ h,
                                                      const int* __restrict__ idx,
                                                      const float* __restrict__ rbf,
                                                      const float* __restrict__ Wrad,
                                                      float* __restrict__ out) {
    __shared__ float Ash[32 * AST];
    __shared__ float Asl[32 * AST];
    __shared__ float Bs[32 * BST];
    __shared__ int js[KK];
    int i = blockIdx.x;
    int tid = threadIdx.x;
    int warp = tid >> 5, lane = tid & 31;
    int gid = lane >> 2, tig = lane & 3;

    {
        int r = tid >> 3;
        int b4 = (tid & 7) * 4;
        float4 v = *reinterpret_cast<const float4*>(rbf + (size_t)i * (KK * BB) + r * BB + b4);
        float4 hi, lo;
        split2f(v.x, hi.x, lo.x);
        split2f(v.y, hi.y, lo.y);
        split2f(v.z, hi.z, lo.z);
        split2f(v.w, hi.w, lo.w);
        *reinterpret_cast<float4*>(&Ash[r * AST + b4]) = hi;
        *reinterpret_cast<float4*>(&Asl[r * AST + b4]) = lo;
    }
    #pragma unroll
    for (int it = 0; it < 8; it++) {
        int idx2 = it * 256 + tid;
        int r = idx2 >> 6;
        int c4 = (idx2 & 63) * 4;
        *reinterpret_cast<float4*>(&Bs[r * BST + c4]) =
            *reinterpret_cast<const float4*>(Wrad + (size_t)r * DD + c4);
    }
    if (tid < KK) js[tid] = idx[i * KK + tid];
    __syncthreads();

    float cf[2][4][4];
    #pragma unroll
    for (int mt = 0; mt < 2; mt++)
        #pragma unroll
        for (int nt = 0; nt < 4; nt++)
            #pragma unroll
            for (int q = 0; q < 4; q++) cf[mt][nt][q] = 0.0f;

    #pragma unroll
    for (int ks = 0; ks < 4; ks++) {
        int kc = ks * 8 + tig;
        unsigned ah[2][4], al[2][4];
        #pragma unroll
        for (int mt = 0; mt < 2; mt++) {
            int r = gid + mt * 16;
            ah[mt][0] = __float_as_uint(Ash[r * AST + kc]);
            ah[mt][1] = __float_as_uint(Ash[(r + 8) * AST + kc]);
            ah[mt][2] = __float_as_uint(Ash[r * AST + kc + 4]);
            ah[mt][3] = __float_as_uint(Ash[(r + 8) * AST + kc + 4]);
            al[mt][0] = __float_as_uint(Asl[r * AST + kc]);
            al[mt][1] = __float_as_uint(Asl[(r + 8) * AST + kc]);
            al[mt][2] = __float_as_uint(Asl[r * AST + kc + 4]);
            al[mt][3] = __float_as_uint(Asl[(r + 8) * AST + kc + 4]);
        }
        unsigned bh[4][2], bl[4][2];
        #pragma unroll
        for (int nt = 0; nt < 4; nt++) {
            int cb = warp * 32 + nt * 8 + gid;
            split2(Bs[(ks * 8 + tig) * BST + cb],     bh[nt][0], bl[nt][0]);
            split2(Bs[(ks * 8 + tig + 4) * BST + cb], bh[nt][1], bl[nt][1]);
        }
        #pragma unroll
        for (int mt = 0; mt < 2; mt++)
            #pragma unroll
            for (int nt = 0; nt < 4; nt++) {
                mma_tf32(cf[mt][nt][0], cf[mt][nt][1], cf[mt][nt][2], cf[mt][nt][3],
                         ah[mt][0], ah[mt][1], ah[mt][2], ah[mt][3],
                         bh[nt][0], bh[nt][1]);
                mma_tf32(cf[mt][nt][0], cf[mt][nt][1], cf[mt][nt][2], cf[mt][nt][3],
                         ah[mt][0], ah[mt][1], ah[mt][2], ah[mt][3],
                         bl[nt][0], bl[nt][1]);
                mma_tf32(cf[mt][nt][0], cf[mt][nt][1], cf[mt][nt][2], cf[mt][nt][3],
                         al[mt][0], al[mt][1], al[mt][2], al[mt][3],
                         bh[nt][0], bh[nt][1]);
            }
    }
    __syncthreads();

    // gather H rows into Bs
    #pragma unroll
    for (int it = 0; it < 8; it++) {
        int idx2 = it * 256 + tid;
        int r = idx2 >> 6;
        int c4 = (idx2 & 63) * 4;
        int j = js[r];
        *reinterpret_cast<float4*>(&Bs[r * BST + c4]) =
            *reinterpret_cast<const float4*>(h + (size_t)j * DD + c4);
    }
    __syncthreads();

    float sacc[4][2];
    #pragma unroll
    for (int nt = 0; nt < 4; nt++) { sacc[nt][0] = 0.0f; sacc[nt][1] = 0.0f; }
    #pragma unroll
    for (int mt = 0; mt < 2; mt++) {
        int r = gid + mt * 16;
        #pragma unroll
        for (int nt = 0; nt < 4; nt++) {
            int c = warp * 32 + nt * 8 + tig * 2;
            sacc[nt][0] += cf[mt][nt][0] * Bs[r * BST + c];
            sacc[nt][1] += cf[mt][nt][1] * Bs[r * BST + c + 1];
            sacc[nt][0] += cf[mt][nt][2] * Bs[(r + 8) * BST + c];
            sacc[nt][1] += cf[mt][nt][3] * Bs[(r + 8) * BST + c + 1];
        }
    }
    #pragma unroll
    for (int o = 4; o <= 16; o <<= 1) {
        #pragma unroll
        for (int nt = 0; nt < 4; nt++) {
            sacc[nt][0] += __shfl_xor_sync(0xFFFFFFFFu, sacc[nt][0], o);
            sacc[nt][1] += __shfl_xor_sync(0xFFFFFFFFu, sacc[nt][1], o);
        }
    }
    if (gid == 0) {
        #pragma unroll
        for (int nt = 0; nt < 4; nt++) {
            int c = warp * 32 + nt * 8 + tig * 2;
            out[(size_t)i * DD + c]     = sacc[nt][0] * (1.0f / KK);
            out[(size_t)i * DD + c + 1] = sacc[nt][1] * (1.0f / KK);
        }
    }
}

// ---------------- coord head ----------------
__global__ void coord_out_kernel(const float* __restrict__ out,
                                 const float* __restrict__ Wc,
                                 float* __restrict__ dout) {
    int i = blockIdx.x;
    int w = threadIdx.x >> 5, lane = threadIdx.x & 31;
    float s = 0.0f;
    for (int d = lane; d < DD; d += 32) s += out[i * DD + d] * Wc[d * 3 + w];
    #pragma unroll
    for (int o = 16; o > 0; o >>= 1) s += __shfl_down_sync(0xFFFFFFFFu, s, o);
    if (lane == 0) dout[(size_t)i * (DD + 3) + DD + w] = s;
}

// ---------------- host launcher ----------------
static void* symaddr(const void* s) {
    void* p = nullptr;
    cudaGetSymbolAddress(&p, s);
    return p;
}

extern "C" void kernel_launch(void* const* d_in, const int* in_sizes, int n_in,
                              void* d_out, int out_size) {
    const float* feat   = (const float*)d_in[0];
    const float* coord  = (const float*)d_in[1];
    const float* mask   = (const float*)d_in[2];
    const float* tptr   = (const float*)d_in[3];
    const float* pos    = (const float*)d_in[4];
    const float* W_in   = (const float*)d_in[5];
    const float* W_self = (const float*)d_in[6];
    const float* W_rad  = (const float*)d_in[7];
    const float* W_conv = (const float*)d_in[8];
    const float* W_cat  = (const float*)d_in[9];
    const float* W_out  = (const float*)d_in[10];
    const float* W_noise= (const float*)d_in[11];
    const float* W_coord= (const float*)d_in[12];
    float* out = (float*)d_out;

    float* p_in     = (float*)symaddr(g_in);
    float* p_cat    = (float*)symaddr(g_cat);
    float* p_hs     = (float*)symaddr(g_hs);
    float* p_msg    = (float*)symaddr(g_msg);
    float* p_states = (float*)symaddr(g_states);
    float* p_out    = (float*)symaddr(g_out);
    int*   p_idx    = (int*)symaddr(g_idx);
    float* p_ed     = (float*)symaddr(g_ed);
    float* p_rbf    = (float*)symaddr(g_rbf);
    float* p_sx     = (float*)symaddr(g_sx);
    float* p_sy     = (float*)symaddr(g_sy);
    float* p_sz     = (float*)symaddr(g_sz);

    static int smem_set = 0;
    if (!smem_set) {
        cudaFuncSetAttribute(gemm_ln_kernel<true>,
                             cudaFuncAttributeMaxDynamicSharedMemorySize, GEMM_SMEM);
        cudaFuncSetAttribute(gemm_ln_kernel<false>,
                             cudaFuncAttributeMaxDynamicSharedMemorySize, GEMM_SMEM);
        smem_set = 1;
    }

    int gg = NN / 32;   // 128 blocks

    build_in_kernel<<<NN, 128>>>(feat, pos, mask, tptr, p_in);
    gemm_ln_kernel<true><<<gg, 512, GEMM_SMEM>>>(p_in, W_in, p_cat, CIN, CIN, 2 * DD,
                                                 mask, p_states, 0);
    soa_kernel<<<NN / 256, 256>>>(coord, p_sx, p_sy, p_sz);
    knn_kernel<<<NN, 256>>>(p_sx, p_sy, p_sz, p_idx, p_ed);
    rbf_kernel<<<(NN * KK * BB + 255) / 256, 256>>>(p_ed, p_rbf);

    for (int l = 0; l < LL; l++) {
        const float* Wself_l = W_self + (size_t)l * DD * DD;
        const float* Wrad_l  = W_rad  + (size_t)l * BB * DD;
        const float* Wconv_l = W_conv + (size_t)l * DD * DD;
        const float* Wcat_l  = W_cat  + (size_t)l * 2 * DD * DD;

        gemm_ln_kernel<true><<<gg, 512, GEMM_SMEM>>>(p_cat, Wself_l, p_hs, DD, 2 * DD, DD,
                                                     nullptr, nullptr, 0);
        msg_mma_kernel<<<NN, 256>>>(p_hs, p_idx, p_rbf, Wrad_l, p_msg);
        gemm_ln_kernel<false><<<gg, 512, GEMM_SMEM>>>(p_msg, Wconv_l, p_cat + DD, DD, DD, 2 * DD,
                                                      nullptr, nullptr, 0);
        gemm_ln_kernel<true><<<gg, 512, GEMM_SMEM>>>(p_cat, Wcat_l, p_cat, 2 * DD, 2 * DD, 2 * DD,
                                                     mask, p_states, l + 1);
    }

    gemm_ln_kernel<false><<<gg, 512, GEMM_SMEM>>>(p_states, W_out, p_out,
                                                  NSTATE * DD, NSTATE * DD, DD,
                                                  nullptr, nullptr, 0);
    gemm_ln_kernel<false><<<gg, 512, GEMM_SMEM>>>(p_out, W_noise, out, DD, DD, DD + 3,
                                                  nullptr, nullptr, 0);
    coord_out_kernel<<<NN, 96>>>(p_out, W_coord, out);
}